// round 16
// baseline (speedup 1.0000x reference)
#include <cuda_runtime.h>
#include <cuda_fp16.h>
#include <cstdint>

#define FDIM 128

// per-node precomputed (fp16): g_Ah = x@W1a + b1 (gather by idx_i),
//                              g_Bh = x@W1b      (gather by idx_j)
__device__ __align__(16) __half g_Ah[50000 * FDIM];
__device__ __align__(16) __half g_Bh[50000 * FDIM];

// ---------------------------------------------------------------------------
// helpers
// ---------------------------------------------------------------------------
__device__ __forceinline__ uint32_t smem_u32(const void* p) {
    uint32_t a;
    asm("{ .reg .u64 t; cvta.to.shared.u64 t, %1; cvt.u32.u64 %0, t; }"
        : "=r"(a) : "l"(p));
    return a;
}
__device__ __forceinline__ void ldsm_x4(uint32_t& a0, uint32_t& a1,
                                        uint32_t& a2, uint32_t& a3, uint32_t addr) {
    asm volatile("ldmatrix.sync.aligned.m8n8.x4.shared.b16 {%0,%1,%2,%3}, [%4];"
                 : "=r"(a0), "=r"(a1), "=r"(a2), "=r"(a3) : "r"(addr));
}
__device__ __forceinline__ void mma_f16(float* d, const uint32_t* a,
                                        uint32_t b0, uint32_t b1) {
    asm volatile("mma.sync.aligned.m16n8k16.row.col.f32.f16.f16.f32 "
                 "{%0,%1,%2,%3}, {%4,%5,%6,%7}, {%8,%9}, {%0,%1,%2,%3};"
                 : "+f"(d[0]), "+f"(d[1]), "+f"(d[2]), "+f"(d[3])
                 : "r"(a[0]), "r"(a[1]), "r"(a[2]), "r"(a[3]), "r"(b0), "r"(b1));
}
__device__ __forceinline__ void cp16(uint32_t saddr, const void* g) {
    asm volatile("cp.async.cg.shared.global [%0], [%1], 16;"
                 :: "r"(saddr), "l"(g) : "memory");
}
#define CP_COMMIT() asm volatile("cp.async.commit_group;" ::: "memory")
#define CP_WAIT2()  asm volatile("cp.async.wait_group 2;" ::: "memory")
#define CP_WAIT1()  asm volatile("cp.async.wait_group 1;" ::: "memory")

// swizzled byte offset in a [rows x 128] fp16 tile
__device__ __forceinline__ uint32_t sw(int row, int chunk16) {
    return (uint32_t)(row * 256 + ((chunk16 ^ (row & 7)) << 4));
}
__device__ __forceinline__ uint32_t pack_h(__half a, __half b) {
    __half2 h = __halves2half2(a, b);
    return *(uint32_t*)&h;
}
__device__ __forceinline__ uint32_t hi_pair(float a, float b) {
    return pack_h(__float2half_rn(a), __float2half_rn(b));
}
// silu via tanh.approx: v * (0.5*tanh(v/2) + 0.5)  — 1 MUFU + 3 FMA
__device__ __forceinline__ float silu_t(float v) {
    float t;
    asm("tanh.approx.f32 %0, %1;" : "=f"(t) : "f"(v * 0.5f));
    return v * fmaf(t, 0.5f, 0.5f);
}

// ---------------------------------------------------------------------------
// precompute (persistent, 512 thr, M=64/tile for wave balance, 1 CTA/SM,
// cp.async double-buffered raw x staging, self-owned conversion):
//   g_Ah = x@W1a + b1 (warps 0-7), g_Bh = x@W1b (warps 8-15)
// warp (within part): mg=(wid>>1)&3 -> rows mg*16..+15, ng=wid&1 -> cols ng*64..+63
// smem: RAW0 0 (2x32K), XIMG 65536 (16K), WA 81920 (32K), WB 114688 (32K)
// ---------------------------------------------------------------------------
#define PCX_RAW0 0
#define PCX_IMG  65536
#define PCX_WA   81920
#define PC_SMEM  147456

extern "C" __global__ void __launch_bounds__(512, 1)
k_precompute_tc(const float* __restrict__ x, const float* __restrict__ W1,
                const float* __restrict__ b1, int n_nodes, int nntiles)
{
    extern __shared__ char smem[];
    const uint32_t sb = smem_u32(smem);
    const int tid  = threadIdx.x;
    const int wid  = tid >> 5;
    const int lane = tid & 31;

    // one-time: W1a/W1b -> fp16 swizzled images (16384 u32 items)
    #pragma unroll
    for (int it = 0; it < 32; ++it) {
        int idx = it * 512 + tid;
        int p   = idx >> 13;
        int rem = idx & 8191;
        int f   = rem >> 6;
        int k0  = (rem & 63) * 2;
        float v0 = W1[(p * 128 + k0) * FDIM + f];
        float v1 = W1[(p * 128 + k0 + 1) * FDIM + f];
        uint32_t off = sw(f, k0 >> 3) + (k0 & 7) * 2;
        *(uint32_t*)(smem + PCX_WA + p * 32768 + off) = hi_pair(v0, v1);
    }

    const int part = wid >> 3;              // 0 -> g_Ah, 1 -> g_Bh
    const int mg   = (wid >> 1) & 3;        // row group: rows mg*16..+15
    const int ng   = wid & 1;               // col half: cols ng*64..+63
    const uint32_t xr   = lane & 7;
    const uint32_t aoff = sb + PCX_IMG + ((uint32_t)(mg * 16 + (lane & 15)) << 8);
    const uint32_t selA = lane >> 4;
    const uint32_t selB = (lane >> 3) & 1;
    const uint32_t bbase = sb + PCX_WA + (uint32_t)part * 32768;
    uint32_t browB[4];
    #pragma unroll
    for (int ntp = 0; ntp < 4; ++ntp)
        browB[ntp] = (uint32_t)(ng * 64 + ntp * 16
                                + ((lane >> 4) & 1) * 8 + (lane & 7)) << 8;
    const int q  = lane >> 2;
    const int cL = (lane & 3) * 2;

    // raw x staging: 64 rows x 512B = 32KB, self-owned 32B units (2/thread)
    auto issue_raw = [&](int t, int b) {
        const float* src = x + (size_t)t * 64 * FDIM;
        uint32_t dst = sb + PCX_RAW0 + (uint32_t)b * 32768;
        #pragma unroll
        for (int it = 0; it < 2; ++it) {
            uint32_t io = (uint32_t)(it * 512 + tid) * 32;
            cp16(dst + io,      (const char*)src + io);
            cp16(dst + io + 16, (const char*)src + io + 16);
        }
    };

    int t = blockIdx.x;
    if (t < nntiles) issue_raw(t, 0);
    CP_COMMIT();

    int pb = 0;
    for (; t < nntiles; t += gridDim.x) {
        const int grow0 = t * 64;

        int nxt = t + gridDim.x;
        if (nxt < nntiles) issue_raw(nxt, pb ^ 1);
        CP_COMMIT();
        CP_WAIT1();             // own raw(t) units complete
        __syncthreads();        // prev tile's XIMG reads done

        // convert own raw units -> XIMG fp16 (self-owned, no pre-barrier)
        {
            char* raw = smem + PCX_RAW0 + pb * 32768;
            #pragma unroll
            for (int it = 0; it < 2; ++it) {
                int id = it * 512 + tid;
                int r = id >> 4, ch = id & 15;
                float4 v0 = *(const float4*)(raw + id * 32);
                float4 v1 = *(const float4*)(raw + id * 32 + 16);
                *(uint4*)(smem + PCX_IMG + sw(r, ch)) =
                    make_uint4(hi_pair(v0.x, v0.y), hi_pair(v0.z, v0.w),
                               hi_pair(v1.x, v1.y), hi_pair(v1.z, v1.w));
            }
        }
        __syncthreads();        // XIMG visible

        float acc[8][4];
        #pragma unroll
        for (int n = 0; n < 8; ++n)
            #pragma unroll
            for (int u = 0; u < 4; ++u) acc[n][u] = 0.f;

        #pragma unroll
        for (int k = 0; k < 8; ++k) {
            uint32_t ah[4];
            uint32_t ao = ((2 * k + selA) ^ xr) << 4;
            ldsm_x4(ah[0], ah[1], ah[2], ah[3], aoff + ao);
            uint32_t co = ((2 * k + selB) ^ xr) << 4;
            #pragma unroll
            for (int ntp = 0; ntp < 4; ++ntp) {
                uint32_t bh[4];
                ldsm_x4(bh[0], bh[1], bh[2], bh[3], bbase + browB[ntp] + co);
                mma_f16(acc[2 * ntp],     ah, bh[0], bh[1]);
                mma_f16(acc[2 * ntp + 1], ah, bh[2], bh[3]);
            }
        }

        __half* dst = part == 0 ? g_Ah : g_Bh;
        int g1 = grow0 + mg * 16 + q;
        int g2 = g1 + 8;
        #pragma unroll
        for (int nt = 0; nt < 8; ++nt) {
            int c = ng * 64 + nt * 8 + cL;
            float bx = 0.f, by = 0.f;
            if (part == 0) {
                float2 bb = *(const float2*)(b1 + c);
                bx = bb.x; by = bb.y;
            }
            if (g1 < n_nodes)
                *(uint32_t*)(dst + g1 * FDIM + c) =
                    hi_pair(acc[nt][0] + bx, acc[nt][1] + by);
            if (g2 < n_nodes)
                *(uint32_t*)(dst + g2 * FDIM + c) =
                    hi_pair(acc[nt][2] + bx, acc[nt][3] + by);
        }
        pb ^= 1;
    }
}

// ---------------------------------------------------------------------------
// pair kernel (persistent, 256 thr, M=64/tile, 2 CTAs/SM — unchanged R15):
//   pre = w_tile @ W1c ; out = silu(pre+gA+gB).W2 + b2   (b1 folded in g_Ah)
// smem: A 0 (16K), RAW0 16384 (2x32K, aliases one-time B image),
//       G 81920 (32K), RED 114688 (1K)
// ---------------------------------------------------------------------------
#define SO_A    0
#define SO_RAW0 16384
#define SO_BIMG 16384
#define SO_G    81920
#define SO_RED  114688
#define KP_SMEM 115712

extern "C" __global__ void __launch_bounds__(256, 2)
k_pairs_tc(const float* __restrict__ w_ij,
           const float* __restrict__ W1,
           const float* __restrict__ W2,
           const float* __restrict__ b2,
           const int* __restrict__ idx_i,
           const int* __restrict__ idx_j,
           float* __restrict__ out,
           int n_pairs, int ntiles)
{
    extern __shared__ char smem[];
    const uint32_t sb = smem_u32(smem);
    const int tid  = threadIdx.x;
    const int wid  = tid >> 5;
    const int lane = tid & 31;

    float* sRed = (float*)(smem + SO_RED);

    const int mg = wid >> 2;
    const int ng = wid & 3;
    const int q  = lane >> 2;
    const int cL = (lane & 3) * 2;
    const uint32_t xr   = lane & 7;
    const uint32_t aoff = sb + SO_A + ((uint32_t)(mg * 32 + (lane & 15)) << 8);
    const uint32_t selA = lane >> 4;
    const uint32_t selB = (lane >> 3) & 1;
    uint32_t browB[2];
    #pragma unroll
    for (int bt = 0; bt < 2; ++bt)
        browB[bt] = (uint32_t)(ng * 32 + bt * 16
                               + ((lane >> 4) & 1) * 8 + (lane & 7)) << 8;

    // one-time: W1c fp16 image in RAW area, load B frags into registers
    #pragma unroll
    for (int it = 0; it < 32; ++it) {
        int idx = it * 256 + tid;
        int f   = idx >> 6;
        int k0  = (idx & 63) * 2;
        float v0 = W1[(256 + k0) * FDIM + f];
        float v1 = W1[(256 + k0 + 1) * FDIM + f];
        uint32_t off = sw(f, k0 >> 3) + (k0 & 7) * 2;
        *(uint32_t*)(smem + SO_BIMG + off) = hi_pair(v0, v1);
    }
    const float b2v = b2[0];
    __syncthreads();

    uint32_t breg[8][8];
    #pragma unroll
    for (int k = 0; k < 8; ++k) {
        uint32_t co = ((2 * k + selB) ^ xr) << 4;
        ldsm_x4(breg[k][0], breg[k][1], breg[k][2], breg[k][3],
                sb + SO_BIMG + browB[0] + co);
        ldsm_x4(breg[k][4], breg[k][5], breg[k][6], breg[k][7],
                sb + SO_BIMG + browB[1] + co);
    }
    __syncthreads();

    float2 w2r[4];
    #pragma unroll
    for (int nt = 0; nt < 4; ++nt)
        w2r[nt] = *(const float2*)(W2 + ng * 32 + nt * 8 + cL);

    auto issue_raw = [&](int t, int b) {
        const char* src = (const char*)w_ij + (size_t)t * 32768;
        uint32_t dst = sb + SO_RAW0 + (uint32_t)b * 32768;
        #pragma unroll
        for (int it = 0; it < 4; ++it) {
            uint32_t io = (uint32_t)(it * 256 + tid) * 32;
            cp16(dst + io,      src + io);
            cp16(dst + io + 16, src + io + 16);
        }
    };
    auto load_idx = [&](int t, int* iv) {
        #pragma unroll
        for (int p = 0; p < 4; ++p) {
            int g  = p * 32 + (tid >> 3);
            int gp = t * 64 + (g & 63);
            iv[p] = __ldg(((g < 64) ? idx_i : idx_j) + gp);
        }
    };
    auto issue_gather = [&](const int* iv) {
        #pragma unroll
        for (int p = 0; p < 4; ++p) {
            int g = p * 32 + (tid >> 3);
            const char* src = (const char*)((g < 64) ? g_Ah : g_Bh)
                              + (size_t)iv[p] * 256;
            uint32_t rowd = sb + SO_G + (uint32_t)g * 256;
            uint32_t swz  = (uint32_t)(g & 7) << 4;
            int c1 = (tid & 7) * 16;
            int c2 = c1 + 128;
            cp16(rowd + ((uint32_t)c1 ^ swz), src + c1);
            cp16(rowd + ((uint32_t)c2 ^ swz), src + c2);
        }
    };

    int tile = blockIdx.x;
    int iv[4];
    if (tile < ntiles) {
        load_idx(tile, iv);
        issue_raw(tile, 0);
    }
    CP_COMMIT();

    int pb = 0;
    for (; tile < ntiles; tile += gridDim.x) {
        const int p0 = tile * 64;

        issue_gather(iv);
        CP_COMMIT();

        int nxt = tile + gridDim.x;
        int ivn[4];
        if (nxt < ntiles) {
            load_idx(nxt, ivn);
            issue_raw(nxt, pb ^ 1);
        }
        CP_COMMIT();

        CP_WAIT2();                 // own raw(t) chunks complete

        // convert OWN raw chunks -> A fp16 image
        {
            char* raw = smem + SO_RAW0 + pb * 32768;
            #pragma unroll
            for (int it = 0; it < 4; ++it) {
                int id = it * 256 + tid;
                int r = id >> 4, ch = id & 15;
                float4 v0 = *(const float4*)(raw + id * 32);
                float4 v1 = *(const float4*)(raw + id * 32 + 16);
                *(uint4*)(smem + SO_A + sw(r, ch)) =
                    make_uint4(hi_pair(v0.x, v0.y), hi_pair(v0.z, v0.w),
                               hi_pair(v1.x, v1.y), hi_pair(v1.z, v1.w));
            }
        }
        __syncthreads();            // (a) A visible to all warps

        // MMA: warp tile 32x32; B from registers
        float acc[8][4];
        #pragma unroll
        for (int n = 0; n < 8; ++n)
            #pragma unroll
            for (int u = 0; u < 4; ++u) acc[n][u] = 0.f;

        #pragma unroll
        for (int k = 0; k < 8; ++k) {
            uint32_t ah0[4], ah1[4];
            uint32_t ao = ((2 * k + selA) ^ xr) << 4;
            ldsm_x4(ah0[0], ah0[1], ah0[2], ah0[3], aoff + ao);
            ldsm_x4(ah1[0], ah1[1], ah1[2], ah1[3], aoff + 4096 + ao);
            #pragma unroll
            for (int bt = 0; bt < 2; ++bt) {
                mma_f16(acc[bt * 2],         ah0, breg[k][bt * 4 + 0], breg[k][bt * 4 + 1]);
                mma_f16(acc[bt * 2 + 1],     ah0, breg[k][bt * 4 + 2], breg[k][bt * 4 + 3]);
                mma_f16(acc[4 + bt * 2],     ah1, breg[k][bt * 4 + 0], breg[k][bt * 4 + 1]);
                mma_f16(acc[4 + bt * 2 + 1], ah1, breg[k][bt * 4 + 2], breg[k][bt * 4 + 3]);
            }
        }

        CP_WAIT1();                 // gather(t) complete (covered by MMA)
        __syncthreads();            // (b) G visible; MMA A-reads retired

        // epilogue: HADD2 addend + tanh silu + W2 dot
        float rs[4] = {0.f, 0.f, 0.f, 0.f};
        #pragma unroll
        for (int mf = 0; mf < 2; ++mf) {
            const int row0_ = mg * 32 + q + mf * 16;
            const int row1_ = row0_ + 8;
            const uint32_t sw0 = (uint32_t)(row0_ & 7) << 4;
            const uint32_t sw1 = (uint32_t)(row1_ & 7) << 4;
            #pragma unroll
            for (int nt = 0; nt < 4; ++nt) {
                const float* a = acc[mf * 4 + nt];
                uint32_t inrow = (uint32_t)(ng * 64 + nt * 16 + cL * 2);
                uint32_t ad0 = SO_G + row0_ * 256 + (inrow ^ sw0);
                uint32_t ad1 = SO_G + row1_ * 256 + (inrow ^ sw1);
                __half2 s0h = __hadd2(*(__half2*)(smem + ad0),
                                      *(__half2*)(smem + ad0 + 16384));
                __half2 s1h = __hadd2(*(__half2*)(smem + ad1),
                                      *(__half2*)(smem + ad1 + 16384));
                float2 s0 = __half22float2(s0h);
                float2 s1 = __half22float2(s1h);
                float v0 = a[0] + s0.x;
                float v1 = a[1] + s0.y;
                float v2 = a[2] + s1.x;
                float v3 = a[3] + s1.y;
                rs[mf * 2]     = fmaf(silu_t(v0), w2r[nt].x,
                                 fmaf(silu_t(v1), w2r[nt].y, rs[mf * 2]));
                rs[mf * 2 + 1] = fmaf(silu_t(v2), w2r[nt].x,
                                 fmaf(silu_t(v3), w2r[nt].y, rs[mf * 2 + 1]));
            }
        }
        #pragma unroll
        for (int rr = 0; rr < 4; ++rr) {
            rs[rr] += __shfl_xor_sync(0xffffffff, rs[rr], 1);
            rs[rr] += __shfl_xor_sync(0xffffffff, rs[rr], 2);
        }
        if ((lane & 3) == 0) {
            #pragma unroll
            for (int rr = 0; rr < 4; ++rr)
                sRed[(mg * 32 + (rr & 1) * 16 + q + (rr >> 1) * 8) * 4 + ng] =
                    rs[(rr & 1) * 2 + (rr >> 1)];
        }
        __syncthreads();            // (c) sRed visible; G reads retired

        if (tid < 64) {
            int o = p0 + tid;
            if (o < n_pairs) {
                float4 r4 = *(const float4*)(sRed + tid * 4);
                out[o] = r4.x + r4.y + r4.z + r4.w + b2v;
            }
        }
        #pragma unroll
        for (int p = 0; p < 4; ++p) iv[p] = ivn[p];
        pb ^= 1;
    }
}

// ---------------------------------------------------------------------------
extern "C" void kernel_launch(void* const* d_in, const int* in_sizes, int n_in,
                              void* d_out, int out_size)
{
    const float* x     = (const float*)d_in[0];
    const float* w_ij  = (const float*)d_in[1];
    const float* W1    = (const float*)d_in[2];
    const float* b1    = (const float*)d_in[3];
    const float* W2    = (const float*)d_in[4];
    const float* b2    = (const float*)d_in[5];
    const int*   idx_i = (const int*)d_in[6];
    const int*   idx_j = (const int*)d_in[7];
    float* out = (float*)d_out;

    const int n_nodes = in_sizes[0] / FDIM;
    const int n_pairs = out_size;
    const int ntiles  = (n_pairs + 63) / 64;
    const int nntiles = (n_nodes + 63) / 64;

    cudaFuncSetAttribute(k_precompute_tc, cudaFuncAttributeMaxDynamicSharedMemorySize, PC_SMEM);
    cudaFuncSetAttribute(k_pairs_tc,      cudaFuncAttributeMaxDynamicSharedMemorySize, KP_SMEM);

    int nsm = 148;
    cudaDeviceGetAttribute(&nsm, cudaDevAttrMultiProcessorCount, 0);
    if (nsm <= 0) nsm = 148;
    int grid1 = nsm < nntiles ? nsm : nntiles;
    int grid2 = 2 * nsm < ntiles ? 2 * nsm : ntiles;

    // 2 launches/iter -> 4th launch overall is k_pairs_tc (ncu capture)
    k_precompute_tc<<<grid1, 512, PC_SMEM>>>(x, W1, b1, n_nodes, nntiles);
    k_pairs_tc<<<grid2, 256, KP_SMEM>>>(w_ij, W1, W2, b2, idx_i, idx_j,
                                        out, n_pairs, ntiles);
}

// round 17
// speedup vs baseline: 1.0104x; 1.0104x over previous
#include <cuda_runtime.h>
#include <cuda_fp16.h>
#include <cstdint>

#define FDIM 128

// per-node precomputed (fp16): g_Ah = x@W1a + b1 (gather by idx_i),
//                              g_Bh = x@W1b      (gather by idx_j)
__device__ __align__(16) __half g_Ah[50000 * FDIM];
__device__ __align__(16) __half g_Bh[50000 * FDIM];

// ---------------------------------------------------------------------------
// helpers
// ---------------------------------------------------------------------------
__device__ __forceinline__ uint32_t smem_u32(const void* p) {
    uint32_t a;
    asm("{ .reg .u64 t; cvta.to.shared.u64 t, %1; cvt.u32.u64 %0, t; }"
        : "=r"(a) : "l"(p));
    return a;
}
__device__ __forceinline__ void ldsm_x4(uint32_t& a0, uint32_t& a1,
                                        uint32_t& a2, uint32_t& a3, uint32_t addr) {
    asm volatile("ldmatrix.sync.aligned.m8n8.x4.shared.b16 {%0,%1,%2,%3}, [%4];"
                 : "=r"(a0), "=r"(a1), "=r"(a2), "=r"(a3) : "r"(addr));
}
__device__ __forceinline__ void mma_f16(float* d, const uint32_t* a,
                                        uint32_t b0, uint32_t b1) {
    asm volatile("mma.sync.aligned.m16n8k16.row.col.f32.f16.f16.f32 "
                 "{%0,%1,%2,%3}, {%4,%5,%6,%7}, {%8,%9}, {%0,%1,%2,%3};"
                 : "+f"(d[0]), "+f"(d[1]), "+f"(d[2]), "+f"(d[3])
                 : "r"(a[0]), "r"(a[1]), "r"(a[2]), "r"(a[3]), "r"(b0), "r"(b1));
}
__device__ __forceinline__ void cp16(uint32_t saddr, const void* g) {
    asm volatile("cp.async.cg.shared.global [%0], [%1], 16;"
                 :: "r"(saddr), "l"(g) : "memory");
}
#define CP_COMMIT() asm volatile("cp.async.commit_group;" ::: "memory")
#define CP_WAIT2()  asm volatile("cp.async.wait_group 2;" ::: "memory")
#define CP_WAIT1()  asm volatile("cp.async.wait_group 1;" ::: "memory")

__device__ __forceinline__ void st_stream(float* p, float v) {
    asm volatile("st.global.cs.f32 [%0], %1;" :: "l"(p), "f"(v) : "memory");
}

// swizzled byte offset in a [rows x 128] fp16 tile
__device__ __forceinline__ uint32_t sw(int row, int chunk16) {
    return (uint32_t)(row * 256 + ((chunk16 ^ (row & 7)) << 4));
}
__device__ __forceinline__ uint32_t pack_h(__half a, __half b) {
    __half2 h = __halves2half2(a, b);
    return *(uint32_t*)&h;
}
__device__ __forceinline__ uint32_t hi_pair(float a, float b) {
    return pack_h(__float2half_rn(a), __float2half_rn(b));
}
// silu via tanh.approx: v * (0.5*tanh(v/2) + 0.5)  — 1 MUFU + 3 FMA
__device__ __forceinline__ float silu_t(float v) {
    float t;
    asm("tanh.approx.f32 %0, %1;" : "=f"(t) : "f"(v * 0.5f));
    return v * fmaf(t, 0.5f, 0.5f);
}

// ---------------------------------------------------------------------------
// precompute (persistent, 512 thr, M=128/tile, 1 CTA/SM — measured-best R15):
//   g_Ah = x@W1a + b1 (warps 0-7), g_Bh = x@W1b (warps 8-15), single-pass fp16
// smem: X 0 (32K), WA 32768, WB 65536   (96KB)
// ---------------------------------------------------------------------------
#define PC_SMEM 98304

extern "C" __global__ void __launch_bounds__(512, 1)
k_precompute_tc(const float* __restrict__ x, const float* __restrict__ W1,
                const float* __restrict__ b1, int n_nodes, int nntiles)
{
    extern __shared__ char smem[];
    const uint32_t sb = smem_u32(smem);
    const int tid  = threadIdx.x;
    const int wid  = tid >> 5;
    const int lane = tid & 31;

    // one-time: W1a/W1b -> fp16 swizzled images
    #pragma unroll
    for (int it = 0; it < 32; ++it) {
        int idx = it * 512 + tid;
        int p   = idx >> 13;
        int rem = idx & 8191;
        int f   = rem >> 6;
        int k0  = (rem & 63) * 2;
        float v0 = W1[(p * 128 + k0) * FDIM + f];
        float v1 = W1[(p * 128 + k0 + 1) * FDIM + f];
        uint32_t off = sw(f, k0 >> 3) + (k0 & 7) * 2;
        *(uint32_t*)(smem + 32768 + p * 32768 + off) = hi_pair(v0, v1);
    }

    const int part = wid >> 3;
    const int rb   = (wid & 7) * 16;
    const uint32_t xr   = lane & 7;
    const uint32_t aoff = sb + ((uint32_t)(rb + (lane & 15)) << 8);
    const uint32_t selA = lane >> 4;
    const uint32_t selB = (lane >> 3) & 1;
    const uint32_t bbase = sb + 32768 + (uint32_t)part * 32768;
    uint32_t browB[8];
    #pragma unroll
    for (int ntp = 0; ntp < 8; ++ntp)
        browB[ntp] = (uint32_t)(ntp * 16 + ((lane >> 4) & 1) * 8 + (lane & 7)) << 8;
    const int q  = lane >> 2;
    const int cL = (lane & 3) * 2;

    for (int t = blockIdx.x; t < nntiles; t += gridDim.x) {
        const int grow0 = t * 128;
        __syncthreads();
        #pragma unroll
        for (int it = 0; it < 8; ++it) {
            int idx = it * 512 + tid;
            int r = idx >> 5, c4 = idx & 31;
            int g = grow0 + r;
            float4 v = make_float4(0.f, 0.f, 0.f, 0.f);
            if (g < n_nodes) v = reinterpret_cast<const float4*>(x)[g * 32 + c4];
            uint32_t off = sw(r, c4 >> 1) + (c4 & 1) * 8;
            *(uint2*)(smem + off) = make_uint2(hi_pair(v.x, v.y), hi_pair(v.z, v.w));
        }
        __syncthreads();

        float acc[16][4];
        #pragma unroll
        for (int n = 0; n < 16; ++n)
            #pragma unroll
            for (int u = 0; u < 4; ++u) acc[n][u] = 0.f;

        #pragma unroll
        for (int k = 0; k < 8; ++k) {
            uint32_t ah[4];
            uint32_t ao = ((2 * k + selA) ^ xr) << 4;
            ldsm_x4(ah[0], ah[1], ah[2], ah[3], aoff + ao);
            uint32_t co = ((2 * k + selB) ^ xr) << 4;
            #pragma unroll
            for (int ntp = 0; ntp < 8; ++ntp) {
                uint32_t bh[4];
                ldsm_x4(bh[0], bh[1], bh[2], bh[3], bbase + browB[ntp] + co);
                mma_f16(acc[2 * ntp],     ah, bh[0], bh[1]);
                mma_f16(acc[2 * ntp + 1], ah, bh[2], bh[3]);
            }
        }

        __half* dst = part == 0 ? g_Ah : g_Bh;
        int g1 = grow0 + rb + q;
        int g2 = g1 + 8;
        #pragma unroll
        for (int nt = 0; nt < 16; ++nt) {
            int c = nt * 8 + cL;
            float bx = 0.f, by = 0.f;
            if (part == 0) {
                float2 bb = *(const float2*)(b1 + c);
                bx = bb.x; by = bb.y;
            }
            if (g1 < n_nodes)
                *(uint32_t*)(dst + g1 * FDIM + c) =
                    hi_pair(acc[nt][0] + bx, acc[nt][1] + by);
            if (g2 < n_nodes)
                *(uint32_t*)(dst + g2 * FDIM + c) =
                    hi_pair(acc[nt][2] + bx, acc[nt][3] + by);
        }
    }
}

// ---------------------------------------------------------------------------
// pair kernel (persistent, 256 thr, M=64/tile, 2 CTAs/SM — measured-best R15,
// + streaming output stores):
//   pre = w_tile @ W1c ; out = silu(pre+gA+gB).W2 + b2   (b1 folded in g_Ah)
// smem: A 0 (16K), RAW0 16384 (2x32K, aliases one-time B image),
//       G 81920 (32K), RED 114688 (1K)
// ---------------------------------------------------------------------------
#define SO_A    0
#define SO_RAW0 16384
#define SO_BIMG 16384
#define SO_G    81920
#define SO_RED  114688
#define KP_SMEM 115712

extern "C" __global__ void __launch_bounds__(256, 2)
k_pairs_tc(const float* __restrict__ w_ij,
           const float* __restrict__ W1,
           const float* __restrict__ W2,
           const float* __restrict__ b2,
           const int* __restrict__ idx_i,
           const int* __restrict__ idx_j,
           float* __restrict__ out,
           int n_pairs, int ntiles)
{
    extern __shared__ char smem[];
    const uint32_t sb = smem_u32(smem);
    const int tid  = threadIdx.x;
    const int wid  = tid >> 5;
    const int lane = tid & 31;

    float* sRed = (float*)(smem + SO_RED);

    const int mg = wid >> 2;
    const int ng = wid & 3;
    const int q  = lane >> 2;
    const int cL = (lane & 3) * 2;
    const uint32_t xr   = lane & 7;
    const uint32_t aoff = sb + SO_A + ((uint32_t)(mg * 32 + (lane & 15)) << 8);
    const uint32_t selA = lane >> 4;
    const uint32_t selB = (lane >> 3) & 1;
    uint32_t browB[2];
    #pragma unroll
    for (int bt = 0; bt < 2; ++bt)
        browB[bt] = (uint32_t)(ng * 32 + bt * 16
                               + ((lane >> 4) & 1) * 8 + (lane & 7)) << 8;

    // one-time: W1c fp16 image in RAW area, load B frags into registers
    #pragma unroll
    for (int it = 0; it < 32; ++it) {
        int idx = it * 256 + tid;
        int f   = idx >> 6;
        int k0  = (idx & 63) * 2;
        float v0 = W1[(256 + k0) * FDIM + f];
        float v1 = W1[(256 + k0 + 1) * FDIM + f];
        uint32_t off = sw(f, k0 >> 3) + (k0 & 7) * 2;
        *(uint32_t*)(smem + SO_BIMG + off) = hi_pair(v0, v1);
    }
    const float b2v = b2[0];
    __syncthreads();

    uint32_t breg[8][8];
    #pragma unroll
    for (int k = 0; k < 8; ++k) {
        uint32_t co = ((2 * k + selB) ^ xr) << 4;
        ldsm_x4(breg[k][0], breg[k][1], breg[k][2], breg[k][3],
                sb + SO_BIMG + browB[0] + co);
        ldsm_x4(breg[k][4], breg[k][5], breg[k][6], breg[k][7],
                sb + SO_BIMG + browB[1] + co);
    }
    __syncthreads();

    float2 w2r[4];
    #pragma unroll
    for (int nt = 0; nt < 4; ++nt)
        w2r[nt] = *(const float2*)(W2 + ng * 32 + nt * 8 + cL);

    auto issue_raw = [&](int t, int b) {
        const char* src = (const char*)w_ij + (size_t)t * 32768;
        uint32_t dst = sb + SO_RAW0 + (uint32_t)b * 32768;
        #pragma unroll
        for (int it = 0; it < 4; ++it) {
            uint32_t io = (uint32_t)(it * 256 + tid) * 32;
            cp16(dst + io,      src + io);
            cp16(dst + io + 16, src + io + 16);
        }
    };
    auto load_idx = [&](int t, int* iv) {
        #pragma unroll
        for (int p = 0; p < 4; ++p) {
            int g  = p * 32 + (tid >> 3);
            int gp = t * 64 + (g & 63);
            iv[p] = __ldg(((g < 64) ? idx_i : idx_j) + gp);
        }
    };
    auto issue_gather = [&](const int* iv) {
        #pragma unroll
        for (int p = 0; p < 4; ++p) {
            int g = p * 32 + (tid >> 3);
            const char* src = (const char*)((g < 64) ? g_Ah : g_Bh)
                              + (size_t)iv[p] * 256;
            uint32_t rowd = sb + SO_G + (uint32_t)g * 256;
            uint32_t swz  = (uint32_t)(g & 7) << 4;
            int c1 = (tid & 7) * 16;
            int c2 = c1 + 128;
            cp16(rowd + ((uint32_t)c1 ^ swz), src + c1);
            cp16(rowd + ((uint32_t)c2 ^ swz), src + c2);
        }
    };

    int tile = blockIdx.x;
    int iv[4];
    if (tile < ntiles) {
        load_idx(tile, iv);
        issue_raw(tile, 0);
    }
    CP_COMMIT();

    int pb = 0;
    for (; tile < ntiles; tile += gridDim.x) {
        const int p0 = tile * 64;

        issue_gather(iv);           // G write-safe: barrier (c) of prev iter
        CP_COMMIT();

        int nxt = tile + gridDim.x;
        int ivn[4];
        if (nxt < ntiles) {
            load_idx(nxt, ivn);
            issue_raw(nxt, pb ^ 1);
        }
        CP_COMMIT();

        CP_WAIT2();                 // own raw(t) chunks complete

        // convert OWN raw chunks -> A fp16 image (self-owned, no pre-barrier)
        {
            char* raw = smem + SO_RAW0 + pb * 32768;
            #pragma unroll
            for (int it = 0; it < 4; ++it) {
                int id = it * 256 + tid;
                int r = id >> 4, ch = id & 15;
                float4 v0 = *(const float4*)(raw + id * 32);
                float4 v1 = *(const float4*)(raw + id * 32 + 16);
                *(uint4*)(smem + SO_A + sw(r, ch)) =
                    make_uint4(hi_pair(v0.x, v0.y), hi_pair(v0.z, v0.w),
                               hi_pair(v1.x, v1.y), hi_pair(v1.z, v1.w));
            }
        }
        __syncthreads();            // (a) A visible to all warps

        // MMA: warp tile 32x32; B from registers
        float acc[8][4];
        #pragma unroll
        for (int n = 0; n < 8; ++n)
            #pragma unroll
            for (int u = 0; u < 4; ++u) acc[n][u] = 0.f;

        #pragma unroll
        for (int k = 0; k < 8; ++k) {
            uint32_t ah0[4], ah1[4];
            uint32_t ao = ((2 * k + selA) ^ xr) << 4;
            ldsm_x4(ah0[0], ah0[1], ah0[2], ah0[3], aoff + ao);
            ldsm_x4(ah1[0], ah1[1], ah1[2], ah1[3], aoff + 4096 + ao);
            #pragma unroll
            for (int bt = 0; bt < 2; ++bt) {
                mma_f16(acc[bt * 2],         ah0, breg[k][bt * 4 + 0], breg[k][bt * 4 + 1]);
                mma_f16(acc[bt * 2 + 1],     ah0, breg[k][bt * 4 + 2], breg[k][bt * 4 + 3]);
                mma_f16(acc[4 + bt * 2],     ah1, breg[k][bt * 4 + 0], breg[k][bt * 4 + 1]);
                mma_f16(acc[4 + bt * 2 + 1], ah1, breg[k][bt * 4 + 2], breg[k][bt * 4 + 3]);
            }
        }

        CP_WAIT1();                 // gather(t) complete (covered by MMA)
        __syncthreads();            // (b) G visible; MMA A-reads retired

        // epilogue: HADD2 addend + tanh silu + W2 dot
        float rs[4] = {0.f, 0.f, 0.f, 0.f};
        #pragma unroll
        for (int mf = 0; mf < 2; ++mf) {
            const int row0_ = mg * 32 + q + mf * 16;
            const int row1_ = row0_ + 8;
            const uint32_t sw0 = (uint32_t)(row0_ & 7) << 4;
            const uint32_t sw1 = (uint32_t)(row1_ & 7) << 4;
            #pragma unroll
            for (int nt = 0; nt < 4; ++nt) {
                const float* a = acc[mf * 4 + nt];
                uint32_t inrow = (uint32_t)(ng * 64 + nt * 16 + cL * 2);
                uint32_t ad0 = SO_G + row0_ * 256 + (inrow ^ sw0);
                uint32_t ad1 = SO_G + row1_ * 256 + (inrow ^ sw1);
                __half2 s0h = __hadd2(*(__half2*)(smem + ad0),
                                      *(__half2*)(smem + ad0 + 16384));
                __half2 s1h = __hadd2(*(__half2*)(smem + ad1),
                                      *(__half2*)(smem + ad1 + 16384));
                float2 s0 = __half22float2(s0h);
                float2 s1 = __half22float2(s1h);
                float v0 = a[0] + s0.x;
                float v1 = a[1] + s0.y;
                float v2 = a[2] + s1.x;
                float v3 = a[3] + s1.y;
                rs[mf * 2]     = fmaf(silu_t(v0), w2r[nt].x,
                                 fmaf(silu_t(v1), w2r[nt].y, rs[mf * 2]));
                rs[mf * 2 + 1] = fmaf(silu_t(v2), w2r[nt].x,
                                 fmaf(silu_t(v3), w2r[nt].y, rs[mf * 2 + 1]));
            }
        }
        #pragma unroll
        for (int rr = 0; rr < 4; ++rr) {
            rs[rr] += __shfl_xor_sync(0xffffffff, rs[rr], 1);
            rs[rr] += __shfl_xor_sync(0xffffffff, rs[rr], 2);
        }
        if ((lane & 3) == 0) {
            #pragma unroll
            for (int rr = 0; rr < 4; ++rr)
                sRed[(mg * 32 + (rr & 1) * 16 + q + (rr >> 1) * 8) * 4 + ng] =
                    rs[(rr & 1) * 2 + (rr >> 1)];
        }
        __syncthreads();            // (c) sRed visible; G reads retired

        if (tid < 64) {
            int o = p0 + tid;
            if (o < n_pairs) {
                float4 r4 = *(const float4*)(sRed + tid * 4);
                st_stream(out + o, r4.x + r4.y + r4.z + r4.w + b2v);
            }
        }
        #pragma unroll
        for (int p = 0; p < 4; ++p) iv[p] = ivn[p];
        pb ^= 1;
    }
}

// ---------------------------------------------------------------------------
extern "C" void kernel_launch(void* const* d_in, const int* in_sizes, int n_in,
                              void* d_out, int out_size)
{
    const float* x     = (const float*)d_in[0];
    const float* w_ij  = (const float*)d_in[1];
    const float* W1    = (const float*)d_in[2];
    const float* b1    = (const float*)d_in[3];
    const float* W2    = (const float*)d_in[4];
    const float* b2    = (const float*)d_in[5];
    const int*   idx_i = (const int*)d_in[6];
    const int*   idx_j = (const int*)d_in[7];
    float* out = (float*)d_out;

    const int n_nodes = in_sizes[0] / FDIM;
    const int n_pairs = out_size;
    const int ntiles  = (n_pairs + 63) / 64;
    const int nntiles = (n_nodes + 127) / 128;

    cudaFuncSetAttribute(k_precompute_tc, cudaFuncAttributeMaxDynamicSharedMemorySize, PC_SMEM);
    cudaFuncSetAttribute(k_pairs_tc,      cudaFuncAttributeMaxDynamicSharedMemorySize, KP_SMEM);

    int nsm = 148;
    cudaDeviceGetAttribute(&nsm, cudaDevAttrMultiProcessorCount, 0);
    if (nsm <= 0) nsm = 148;
    int grid1 = nsm < nntiles ? nsm : nntiles;
    int grid2 = 2 * nsm < ntiles ? 2 * nsm : ntiles;

    // 2 launches/iter -> 4th launch overall is k_pairs_tc (ncu capture)
    k_precompute_tc<<<grid1, 512, PC_SMEM>>>(x, W1, b1, n_nodes, nntiles);
    k_pairs_tc<<<grid2, 256, KP_SMEM>>>(w_ij, W1, W2, b2, idx_i, idx_j,
                                        out, n_pairs, ntiles);
}